// round 2
// baseline (speedup 1.0000x reference)
#include <cuda_runtime.h>
#include <math.h>
#include <stdint.h>

// Problem constants
#define Bb 2
#define Tt 2048
#define Dd 2048
#define Hh 16
#define HDim 128
#define Mrows (Bb*Tt)   // 4096

// Scratch (device globals; no allocation allowed)
__device__ float g_q[Bb*Hh*Tt*HDim];   // (B,H,T,HD)
__device__ float g_k[Bb*Hh*Tt*HDim];
__device__ float g_v[Bb*Hh*Tt*HDim];
__device__ float g_ctx[Bb*Tt*Dd];      // (B,T,D)

__device__ __forceinline__ uint32_t f2tf32(float x) {
    uint32_t r;
    asm("cvt.rna.tf32.f32 %0, %1;" : "=r"(r) : "f"(x));
    return r;
}

// ---------------------------------------------------------------------------
// TF32 tensor-core GEMM: C[m,n] = sum_k A[m,k] * W[n,k]
// A: M x K row-major, W: N x K row-major. M=4096, N=2048, K=2048.
// Block tile 128x128, BK=16, 256 threads = 8 warps (4 m x 2 n),
// warp tile 32x64 = 2 x 8 tiles of m16n8k8.
// mode 0: C row-major [m*N + n]
// mode 1: scatter to (B,H,T,HD)
// ---------------------------------------------------------------------------
#define LDT 136   // smem row stride in words (mod 32 == 8 -> conflict-free frags)

__global__ __launch_bounds__(256, 2)
void gemm_tf32_kernel(const float* __restrict__ A, const float* __restrict__ W,
                      float* __restrict__ out, int mode)
{
    const int K = Dd;
    const int N = Dd;
    __shared__ uint32_t As[16 * LDT];   // As[k][m], m in [0,128)
    __shared__ uint32_t Bs[16 * LDT];   // Bs[k][n], n in [0,128)

    const int tid    = threadIdx.x;
    const int lane   = tid & 31;
    const int warp   = tid >> 5;        // 0..7
    const int warp_m = warp >> 1;       // 0..3
    const int warp_n = warp & 1;        // 0..1
    const int g      = lane >> 2;       // 0..7
    const int tg     = lane & 3;        // 0..3

    const int m0 = blockIdx.y * 128;
    const int n0 = blockIdx.x * 128;

    const int m_warp = warp_m * 32;
    const int n_warp = warp_n * 64;

    float acc[2][8][4];
#pragma unroll
    for (int mt = 0; mt < 2; mt++)
#pragma unroll
        for (int nt = 0; nt < 8; nt++)
#pragma unroll
            for (int c = 0; c < 4; c++) acc[mt][nt][c] = 0.0f;

    const float* Aptr = A + (size_t)m0 * K;
    const float* Wptr = W + (size_t)n0 * K;

    for (int kt = 0; kt < K; kt += 16) {
        // Load A,W tiles -> smem transposed [k][m]/[k][n], converted to tf32
#pragma unroll
        for (int it = 0; it < 2; it++) {
            int f   = tid + it * 256;      // 0..511
            int row = f >> 2;              // 0..127
            int k4  = (f & 3) * 4;         // 0,4,8,12
            float4 av = *(const float4*)(Aptr + (size_t)row * K + kt + k4);
            As[(k4 + 0) * LDT + row] = f2tf32(av.x);
            As[(k4 + 1) * LDT + row] = f2tf32(av.y);
            As[(k4 + 2) * LDT + row] = f2tf32(av.z);
            As[(k4 + 3) * LDT + row] = f2tf32(av.w);
            float4 bv = *(const float4*)(Wptr + (size_t)row * K + kt + k4);
            Bs[(k4 + 0) * LDT + row] = f2tf32(bv.x);
            Bs[(k4 + 1) * LDT + row] = f2tf32(bv.y);
            Bs[(k4 + 2) * LDT + row] = f2tf32(bv.z);
            Bs[(k4 + 3) * LDT + row] = f2tf32(bv.w);
        }
        __syncthreads();

#pragma unroll
        for (int k0 = 0; k0 < 16; k0 += 8) {
            // A fragments: 2 m-tiles
            uint32_t a[2][4];
#pragma unroll
            for (int mt = 0; mt < 2; mt++) {
                int mb = m_warp + mt * 16;
                a[mt][0] = As[(k0 + tg)     * LDT + mb + g];
                a[mt][1] = As[(k0 + tg)     * LDT + mb + g + 8];
                a[mt][2] = As[(k0 + tg + 4) * LDT + mb + g];
                a[mt][3] = As[(k0 + tg + 4) * LDT + mb + g + 8];
            }
            // B fragments: 8 n-tiles
            uint32_t b[8][2];
#pragma unroll
            for (int nt = 0; nt < 8; nt++) {
                int nb = n_warp + nt * 8;
                b[nt][0] = Bs[(k0 + tg)     * LDT + nb + g];
                b[nt][1] = Bs[(k0 + tg + 4) * LDT + nb + g];
            }
#pragma unroll
            for (int mt = 0; mt < 2; mt++)
#pragma unroll
                for (int nt = 0; nt < 8; nt++) {
                    asm volatile(
                        "mma.sync.aligned.m16n8k8.row.col.f32.tf32.tf32.f32 "
                        "{%0,%1,%2,%3}, {%4,%5,%6,%7}, {%8,%9}, {%0,%1,%2,%3};"
                        : "+f"(acc[mt][nt][0]), "+f"(acc[mt][nt][1]),
                          "+f"(acc[mt][nt][2]), "+f"(acc[mt][nt][3])
                        : "r"(a[mt][0]), "r"(a[mt][1]), "r"(a[mt][2]), "r"(a[mt][3]),
                          "r"(b[nt][0]), "r"(b[nt][1]));
                }
        }
        __syncthreads();
    }

    // Epilogue
    // C element mapping: row = m0 + m_warp + mt*16 + g (+8 for c2,c3)
    //                    col = n0 + n_warp + nt*8 + tg*2 + {0,1}
    if (mode == 0) {
#pragma unroll
        for (int mt = 0; mt < 2; mt++) {
#pragma unroll
            for (int half = 0; half < 2; half++) {
                int m = m0 + m_warp + mt * 16 + g + half * 8;
                float* rowp = out + (size_t)m * N + n0 + n_warp + tg * 2;
#pragma unroll
                for (int nt = 0; nt < 8; nt++) {
                    float2 w = make_float2(acc[mt][nt][half * 2], acc[mt][nt][half * 2 + 1]);
                    *(float2*)(rowp + nt * 8) = w;
                }
            }
        }
    } else {
        int h = n0 >> 7;   // whole 128-wide tile belongs to one head
#pragma unroll
        for (int mt = 0; mt < 2; mt++) {
#pragma unroll
            for (int half = 0; half < 2; half++) {
                int m  = m0 + m_warp + mt * 16 + g + half * 8;
                int bI = m >> 11;            // m / T
                int t  = m & (Tt - 1);       // m % T
                float* rowp = out + (((size_t)(bI * Hh + h) * Tt + t) * HDim)
                              + n_warp + tg * 2;
#pragma unroll
                for (int nt = 0; nt < 8; nt++) {
                    float2 w = make_float2(acc[mt][nt][half * 2], acc[mt][nt][half * 2 + 1]);
                    *(float2*)(rowp + nt * 8) = w;
                }
            }
        }
    }
}

// ---------------------------------------------------------------------------
// RoPE over q and k in (B,H,T,HD) layout.
// ---------------------------------------------------------------------------
__global__ __launch_bounds__(256)
void rope_kernel(float* __restrict__ q, float* __restrict__ k,
                 const float* __restrict__ cosp, const float* __restrict__ sinp)
{
    int gid = blockIdx.x * 256 + threadIdx.x;     // 0 .. B*H*T*64-1
    int row = gid >> 6;                            // (b*H + h)*T + t
    int i   = gid & 63;
    int t   = row & (Tt - 1);

    float c1 = cosp[t * HDim + i];
    float s1 = sinp[t * HDim + i];
    float c2 = cosp[t * HDim + 64 + i];
    float s2 = sinp[t * HDim + 64 + i];

    float* qp = q + (size_t)row * HDim;
    float qa = qp[i], qb = qp[i + 64];
    qp[i]      = c1 * qa - s1 * qb;
    qp[i + 64] = c2 * qb + s2 * qa;

    float* kp = k + (size_t)row * HDim;
    float ka = kp[i], kb = kp[i + 64];
    kp[i]      = c1 * ka - s1 * kb;
    kp[i + 64] = c2 * kb + s2 * ka;
}

// ---------------------------------------------------------------------------
// Flash attention (causal), fp32.
// Grid: (T/64, B*H). 256 threads. BM=BN=64, HD=128.
// ---------------------------------------------------------------------------
#define FBM 64
#define FBN 64
#define QS_LD 132
#define PS_LD 68

__global__ __launch_bounds__(256, 1)
void flash_kernel(const float* __restrict__ q, const float* __restrict__ k,
                  const float* __restrict__ v, float* __restrict__ ctx)
{
    extern __shared__ float sm[];
    float* Qs = sm;                       // 64*132
    float* Ks = Qs + FBM * QS_LD;         // 64*132
    float* Vs = Ks + FBN * QS_LD;         // 64*132
    float* Ps = Vs + FBN * QS_LD;         // 64*68

    const int tid = threadIdx.x;
    const int qb  = blockIdx.x;           // q tile index, 0..31
    const int bh  = blockIdx.y;           // 0..31
    const int b   = bh >> 4;
    const int h   = bh & 15;

    const float scale = 0.08838834764831845f;  // 1/sqrt(128)

    const float* qbase = q + ((size_t)bh * Tt + (size_t)qb * FBM) * HDim;
    const float* kbase = k + (size_t)bh * Tt * HDim;
    const float* vbase = v + (size_t)bh * Tt * HDim;

    // Load Q tile (scaled)
#pragma unroll
    for (int it = 0; it < 8; it++) {
        int f  = tid + it * 256;          // 0..2047 float4 slots
        int r  = f >> 5;                  // row 0..63
        int c4 = (f & 31) * 4;            // 0..124
        float4 val = *(const float4*)(qbase + (size_t)r * HDim + c4);
        val.x *= scale; val.y *= scale; val.z *= scale; val.w *= scale;
        *(float4*)&Qs[r * QS_LD + c4] = val;
    }

    const int ry = tid >> 4;   // 0..15 -> rows ry*4 .. ry*4+3
    const int cx = tid & 15;   // 0..15 -> S cols cx*4.., O cols cx*8..

    float m_st[4], l_st[4];
    float o[4][8];
#pragma unroll
    for (int i = 0; i < 4; i++) {
        m_st[i] = -INFINITY;
        l_st[i] = 0.0f;
#pragma unroll
        for (int c = 0; c < 8; c++) o[i][c] = 0.0f;
    }

    for (int kb = 0; kb <= qb; kb++) {
        __syncthreads();   // prior PV reads of Ks/Vs/Ps done before overwrite
        // Load K,V tiles
#pragma unroll
        for (int it = 0; it < 8; it++) {
            int f  = tid + it * 256;
            int r  = f >> 5;
            int c4 = (f & 31) * 4;
            size_t goff = ((size_t)(kb * FBN + r)) * HDim + c4;
            *(float4*)&Ks[r * QS_LD + c4] = *(const float4*)(kbase + goff);
            *(float4*)&Vs[r * QS_LD + c4] = *(const float4*)(vbase + goff);
        }
        __syncthreads();

        // S = Q K^T (4x4 per thread)
        float s[4][4];
#pragma unroll
        for (int i = 0; i < 4; i++)
#pragma unroll
            for (int j = 0; j < 4; j++) s[i][j] = 0.0f;

        for (int kk = 0; kk < HDim; kk += 4) {
            float4 qv[4], kv[4];
#pragma unroll
            for (int i = 0; i < 4; i++)
                qv[i] = *(float4*)&Qs[(ry * 4 + i) * QS_LD + kk];
#pragma unroll
            for (int j = 0; j < 4; j++)
                kv[j] = *(float4*)&Ks[(cx * 4 + j) * QS_LD + kk];
#pragma unroll
            for (int i = 0; i < 4; i++)
#pragma unroll
                for (int j = 0; j < 4; j++) {
                    s[i][j] += qv[i].x * kv[j].x;
                    s[i][j] += qv[i].y * kv[j].y;
                    s[i][j] += qv[i].z * kv[j].z;
                    s[i][j] += qv[i].w * kv[j].w;
                }
        }

        // Causal mask on diagonal tile + online softmax
        const bool diag = (kb == qb);
#pragma unroll
        for (int i = 0; i < 4; i++) {
            int r = ry * 4 + i;
            if (diag) {
#pragma unroll
                for (int j = 0; j < 4; j++)
                    if (cx * 4 + j > r) s[i][j] = -INFINITY;
            }
            float mt = fmaxf(fmaxf(s[i][0], s[i][1]), fmaxf(s[i][2], s[i][3]));
#pragma unroll
            for (int off = 8; off > 0; off >>= 1)
                mt = fmaxf(mt, __shfl_xor_sync(0xffffffffu, mt, off));
            float mnew  = fmaxf(m_st[i], mt);
            float alpha = expf(m_st[i] - mnew);
            float psum  = 0.0f;
#pragma unroll
            for (int j = 0; j < 4; j++) {
                float p = expf(s[i][j] - mnew);
                Ps[r * PS_LD + cx * 4 + j] = p;
                psum += p;
            }
#pragma unroll
            for (int off = 8; off > 0; off >>= 1)
                psum += __shfl_xor_sync(0xffffffffu, psum, off);
            l_st[i] = l_st[i] * alpha + psum;
            m_st[i] = mnew;
#pragma unroll
            for (int c = 0; c < 8; c++) o[i][c] *= alpha;
        }
        __syncthreads();

        // O += P * V  (rows ry*4.., cols cx*8..)
        for (int kk = 0; kk < FBN; kk++) {
            float pv0 = Ps[(ry * 4 + 0) * PS_LD + kk];
            float pv1 = Ps[(ry * 4 + 1) * PS_LD + kk];
            float pv2 = Ps[(ry * 4 + 2) * PS_LD + kk];
            float pv3 = Ps[(ry * 4 + 3) * PS_LD + kk];
            float4 v0 = *(float4*)&Vs[kk * QS_LD + cx * 8];
            float4 v1 = *(float4*)&Vs[kk * QS_LD + cx * 8 + 4];
            o[0][0] += pv0 * v0.x; o[0][1] += pv0 * v0.y; o[0][2] += pv0 * v0.z; o[0][3] += pv0 * v0.w;
            o[0][4] += pv0 * v1.x; o[0][5] += pv0 * v1.y; o[0][6] += pv0 * v1.z; o[0][7] += pv0 * v1.w;
            o[1][0] += pv1 * v0.x; o[1][1] += pv1 * v0.y; o[1][2] += pv1 * v0.z; o[1][3] += pv1 * v0.w;
            o[1][4] += pv1 * v1.x; o[1][5] += pv1 * v1.y; o[1][6] += pv1 * v1.z; o[1][7] += pv1 * v1.w;
            o[2][0] += pv2 * v0.x; o[2][1] += pv2 * v0.y; o[2][2] += pv2 * v0.z; o[2][3] += pv2 * v0.w;
            o[2][4] += pv2 * v1.x; o[2][5] += pv2 * v1.y; o[2][6] += pv2 * v1.z; o[2][7] += pv2 * v1.w;
            o[3][0] += pv3 * v0.x; o[3][1] += pv3 * v0.y; o[3][2] += pv3 * v0.z; o[3][3] += pv3 * v0.w;
            o[3][4] += pv3 * v1.x; o[3][5] += pv3 * v1.y; o[3][6] += pv3 * v1.z; o[3][7] += pv3 * v1.w;
        }
    }

    // Epilogue: normalize and write ctx (B,T,D)
#pragma unroll
    for (int i = 0; i < 4; i++) {
        int r = ry * 4 + i;
        int t = qb * FBM + r;
        float inv = 1.0f / l_st[i];
        float* p = ctx + ((size_t)(b * Tt + t)) * Dd + h * HDim + cx * 8;
        float4 w0 = make_float4(o[i][0] * inv, o[i][1] * inv, o[i][2] * inv, o[i][3] * inv);
        float4 w1 = make_float4(o[i][4] * inv, o[i][5] * inv, o[i][6] * inv, o[i][7] * inv);
        *(float4*)(p)     = w0;
        *(float4*)(p + 4) = w1;
    }
}

// ---------------------------------------------------------------------------
// Launch
// ---------------------------------------------------------------------------
extern "C" void kernel_launch(void* const* d_in, const int* in_sizes, int n_in,
                              void* d_out, int out_size)
{
    const float* x        = (const float*)d_in[0];
    const float* Wq       = (const float*)d_in[1];
    const float* Wk       = (const float*)d_in[2];
    const float* Wv       = (const float*)d_in[3];
    const float* Wo       = (const float*)d_in[4];
    const float* rope_cos = (const float*)d_in[5];
    const float* rope_sin = (const float*)d_in[6];
    float* out = (float*)d_out;

    float *qp, *kp, *vp, *ctxp;
    cudaGetSymbolAddress((void**)&qp,   g_q);
    cudaGetSymbolAddress((void**)&kp,   g_k);
    cudaGetSymbolAddress((void**)&vp,   g_v);
    cudaGetSymbolAddress((void**)&ctxp, g_ctx);

    const int FLASH_SMEM = (3 * FBM * QS_LD + FBM * PS_LD) * (int)sizeof(float); // 118784 B
    cudaFuncSetAttribute(flash_kernel, cudaFuncAttributeMaxDynamicSharedMemorySize, FLASH_SMEM);

    dim3 ggrid(Dd / 128, Mrows / 128);   // (16, 32)
    // QKV projections with scatter to (B,H,T,HD)
    gemm_tf32_kernel<<<ggrid, 256>>>(x, Wq, qp, 1);
    gemm_tf32_kernel<<<ggrid, 256>>>(x, Wk, kp, 1);
    gemm_tf32_kernel<<<ggrid, 256>>>(x, Wv, vp, 1);

    // RoPE on q,k
    int rope_threads_total = Bb * Hh * Tt * 64;
    rope_kernel<<<rope_threads_total / 256, 256>>>(qp, kp, rope_cos, rope_sin);

    // Flash attention -> ctx (B,T,D)
    dim3 fgrid(Tt / FBM, Bb * Hh);       // (32, 32)
    flash_kernel<<<fgrid, 256, FLASH_SMEM>>>(qp, kp, vp, ctxp);

    // Output projection
    gemm_tf32_kernel<<<ggrid, 256>>>(ctxp, Wo, out, 0);
}

// round 4
// speedup vs baseline: 1.7964x; 1.7964x over previous
#include <cuda_runtime.h>
#include <math.h>
#include <stdint.h>

// Problem constants
#define Bb 2
#define Tt 2048
#define Dd 2048
#define Hh 16
#define HDim 128
#define Mrows (Bb*Tt)   // 4096

// Scratch (device globals; no allocation allowed)
__device__ float g_q[Bb*Hh*Tt*HDim];   // (B,H,T,HD)
__device__ float g_k[Bb*Hh*Tt*HDim];
__device__ float g_v[Bb*Hh*Tt*HDim];
__device__ float g_ctx[Bb*Tt*Dd];      // (B,T,D)

__device__ __forceinline__ uint32_t f2tf32(float x) {
    uint32_t r;
    asm("cvt.rna.tf32.f32 %0, %1;" : "=r"(r) : "f"(x));
    return r;
}

__device__ __forceinline__ void mma_tf32(float c[4],
                                         uint32_t a0, uint32_t a1, uint32_t a2, uint32_t a3,
                                         uint32_t b0, uint32_t b1) {
    asm volatile(
        "mma.sync.aligned.m16n8k8.row.col.f32.tf32.tf32.f32 "
        "{%0,%1,%2,%3}, {%4,%5,%6,%7}, {%8,%9}, {%0,%1,%2,%3};"
        : "+f"(c[0]), "+f"(c[1]), "+f"(c[2]), "+f"(c[3])
        : "r"(a0), "r"(a1), "r"(a2), "r"(a3), "r"(b0), "r"(b1));
}

// Fast exp2 on fma/alu pipes (avoids MUFU throughput wall).
// Degree-5 Taylor of 2^f on [0,1): rel err <= ~1.6e-4. Clamp keeps NaN out of
// the -inf - m path and keeps the exponent splice in normal range.
__device__ __forceinline__ float fexp2(float x) {
    x = fmaxf(x, -126.0f);
    float xi = floorf(x);
    float f  = x - xi;
    float p  = 0.0013333558f;
    p = fmaf(p, f, 0.0096181291f);
    p = fmaf(p, f, 0.0555041086f);
    p = fmaf(p, f, 0.2402265069f);
    p = fmaf(p, f, 0.6931471806f);
    p = fmaf(p, f, 1.0f);
    return __int_as_float(__float_as_int(p) + (((int)xi) << 23));
}

// ---------------------------------------------------------------------------
// TF32 tensor-core GEMM: C[m,n] = sum_k A[m,k] * W[n,k]  (validated in R2)
// ---------------------------------------------------------------------------
#define LDT 136

__global__ __launch_bounds__(256, 2)
void gemm_tf32_kernel(const float* __restrict__ A, const float* __restrict__ W,
                      float* __restrict__ out, int mode)
{
    const int K = Dd;
    const int N = Dd;
    __shared__ uint32_t As[16 * LDT];
    __shared__ uint32_t Bs[16 * LDT];

    const int tid    = threadIdx.x;
    const int lane   = tid & 31;
    const int warp   = tid >> 5;
    const int warp_m = warp >> 1;
    const int warp_n = warp & 1;
    const int g      = lane >> 2;
    const int tg     = lane & 3;

    const int m0 = blockIdx.y * 128;
    const int n0 = blockIdx.x * 128;
    const int m_warp = warp_m * 32;
    const int n_warp = warp_n * 64;

    float acc[2][8][4];
#pragma unroll
    for (int mt = 0; mt < 2; mt++)
#pragma unroll
        for (int nt = 0; nt < 8; nt++)
#pragma unroll
            for (int c = 0; c < 4; c++) acc[mt][nt][c] = 0.0f;

    const float* Aptr = A + (size_t)m0 * K;
    const float* Wptr = W + (size_t)n0 * K;

    for (int kt = 0; kt < K; kt += 16) {
#pragma unroll
        for (int it = 0; it < 2; it++) {
            int f   = tid + it * 256;
            int row = f >> 2;
            int k4  = (f & 3) * 4;
            float4 av = *(const float4*)(Aptr + (size_t)row * K + kt + k4);
            As[(k4 + 0) * LDT + row] = f2tf32(av.x);
            As[(k4 + 1) * LDT + row] = f2tf32(av.y);
            As[(k4 + 2) * LDT + row] = f2tf32(av.z);
            As[(k4 + 3) * LDT + row] = f2tf32(av.w);
            float4 bv = *(const float4*)(Wptr + (size_t)row * K + kt + k4);
            Bs[(k4 + 0) * LDT + row] = f2tf32(bv.x);
            Bs[(k4 + 1) * LDT + row] = f2tf32(bv.y);
            Bs[(k4 + 2) * LDT + row] = f2tf32(bv.z);
            Bs[(k4 + 3) * LDT + row] = f2tf32(bv.w);
        }
        __syncthreads();

#pragma unroll
        for (int k0 = 0; k0 < 16; k0 += 8) {
            uint32_t a[2][4];
#pragma unroll
            for (int mt = 0; mt < 2; mt++) {
                int mb = m_warp + mt * 16;
                a[mt][0] = As[(k0 + tg)     * LDT + mb + g];
                a[mt][1] = As[(k0 + tg)     * LDT + mb + g + 8];
                a[mt][2] = As[(k0 + tg + 4) * LDT + mb + g];
                a[mt][3] = As[(k0 + tg + 4) * LDT + mb + g + 8];
            }
            uint32_t b[8][2];
#pragma unroll
            for (int nt = 0; nt < 8; nt++) {
                int nb = n_warp + nt * 8;
                b[nt][0] = Bs[(k0 + tg)     * LDT + nb + g];
                b[nt][1] = Bs[(k0 + tg + 4) * LDT + nb + g];
            }
#pragma unroll
            for (int mt = 0; mt < 2; mt++)
#pragma unroll
                for (int nt = 0; nt < 8; nt++)
                    mma_tf32(acc[mt][nt], a[mt][0], a[mt][1], a[mt][2], a[mt][3],
                             b[nt][0], b[nt][1]);
        }
        __syncthreads();
    }

    if (mode == 0) {
#pragma unroll
        for (int mt = 0; mt < 2; mt++) {
#pragma unroll
            for (int half = 0; half < 2; half++) {
                int m = m0 + m_warp + mt * 16 + g + half * 8;
                float* rowp = out + (size_t)m * N + n0 + n_warp + tg * 2;
#pragma unroll
                for (int nt = 0; nt < 8; nt++) {
                    float2 w = make_float2(acc[mt][nt][half * 2], acc[mt][nt][half * 2 + 1]);
                    *(float2*)(rowp + nt * 8) = w;
                }
            }
        }
    } else {
        int h = n0 >> 7;
#pragma unroll
        for (int mt = 0; mt < 2; mt++) {
#pragma unroll
            for (int half = 0; half < 2; half++) {
                int m  = m0 + m_warp + mt * 16 + g + half * 8;
                int bI = m >> 11;
                int t  = m & (Tt - 1);
                float* rowp = out + (((size_t)(bI * Hh + h) * Tt + t) * HDim)
                              + n_warp + tg * 2;
#pragma unroll
                for (int nt = 0; nt < 8; nt++) {
                    float2 w = make_float2(acc[mt][nt][half * 2], acc[mt][nt][half * 2 + 1]);
                    *(float2*)(rowp + nt * 8) = w;
                }
            }
        }
    }
}

// ---------------------------------------------------------------------------
// RoPE over q and k in (B,H,T,HD) layout.
// ---------------------------------------------------------------------------
__global__ __launch_bounds__(256)
void rope_kernel(float* __restrict__ q, float* __restrict__ k,
                 const float* __restrict__ cosp, const float* __restrict__ sinp)
{
    int gid = blockIdx.x * 256 + threadIdx.x;
    int row = gid >> 6;
    int i   = gid & 63;
    int t   = row & (Tt - 1);

    float c1 = cosp[t * HDim + i];
    float s1 = sinp[t * HDim + i];
    float c2 = cosp[t * HDim + 64 + i];
    float s2 = sinp[t * HDim + 64 + i];

    float* qp = q + (size_t)row * HDim;
    float qa = qp[i], qb = qp[i + 64];
    qp[i]      = c1 * qa - s1 * qb;
    qp[i + 64] = c2 * qb + s2 * qa;

    float* kp = k + (size_t)row * HDim;
    float ka = kp[i], kb = kp[i + 64];
    kp[i]      = c1 * ka - s1 * kb;
    kp[i + 64] = c2 * kb + s2 * ka;
}

// ---------------------------------------------------------------------------
// Flash attention (causal), tf32 tensor cores.
// BM=128 rows per CTA, BN=64 keys per tile, HD=128.
// 8 warps; warp w owns rows [16w, 16w+16): full rows -> warp-local softmax.
// Smem layouts (uint32 tf32):
//   Qs [128][140] natural  (stride 140 == 12 mod 32: frag reads conflict-free)
//   Ks [ 64][140] natural
//   Vs [ 64][136] natural  (stride 136 == 8 mod 32: frag reads conflict-free)
//   Ps [128][ 76] (stride 76 == 12 mod 32)
// ---------------------------------------------------------------------------
#define FBM 128
#define FBN 64
#define LDQ 140
#define LDV 136
#define LDP 76

__global__ __launch_bounds__(256, 1)
void flash_mma_kernel(const float* __restrict__ q, const float* __restrict__ k,
                      const float* __restrict__ v, float* __restrict__ ctx)
{
    extern __shared__ uint32_t smu[];
    uint32_t* Qs = smu;                    // 128*140
    uint32_t* Ks = Qs + FBM * LDQ;         // 64*140
    uint32_t* Vs = Ks + FBN * LDQ;         // 64*136
    uint32_t* Ps = Vs + FBN * LDV;         // 128*76

    const int tid  = threadIdx.x;
    const int lane = tid & 31;
    const int w    = tid >> 5;             // warp 0..7 -> rows 16w..16w+15
    const int g    = lane >> 2;            // 0..7
    const int tg   = lane & 3;             // 0..3

    const int qb = blockIdx.x;             // 0..15 (q tile of 128 rows)
    const int bh = blockIdx.y;             // 0..31
    const int b  = bh >> 4;
    const int h  = bh & 15;

    // scale * log2(e): softmax done in base-2 domain
    const float qscale = 0.08838834764831845f * 1.4426950408889634f;

    const float* qbase = q + ((size_t)bh * Tt + (size_t)qb * FBM) * HDim;
    const float* kbase = k + (size_t)bh * Tt * HDim;
    const float* vbase = v + (size_t)bh * Tt * HDim;

    // Load Q tile (natural layout, scaled, tf32)
#pragma unroll
    for (int it = 0; it < 16; it++) {
        int f  = tid + it * 256;           // 0..4095
        int r  = f >> 5;                   // 0..127
        int c4 = (f & 31) * 4;
        float4 val = *(const float4*)(qbase + (size_t)r * HDim + c4);
        Qs[r * LDQ + c4 + 0] = f2tf32(val.x * qscale);
        Qs[r * LDQ + c4 + 1] = f2tf32(val.y * qscale);
        Qs[r * LDQ + c4 + 2] = f2tf32(val.z * qscale);
        Qs[r * LDQ + c4 + 3] = f2tf32(val.w * qscale);
    }

    const int row0 = 16 * w + g;           // local row for c0,c1; row0+8 for c2,c3

    float m0 = -INFINITY, m1 = -INFINITY;
    float l0 = 0.0f, l1 = 0.0f;
    float o[16][4];
#pragma unroll
    for (int nt = 0; nt < 16; nt++)
#pragma unroll
        for (int c = 0; c < 4; c++) o[nt][c] = 0.0f;

    const int nkb = 2 * qb + 2;
    for (int kb = 0; kb < nkb; kb++) {
        __syncthreads();   // all warps done with Ks/Vs of previous iteration
        // Load K,V tiles (coalesced, natural layout, tf32)
#pragma unroll
        for (int it = 0; it < 8; it++) {
            int f  = tid + it * 256;       // 0..2047
            int r  = f >> 5;               // 0..63
            int c4 = (f & 31) * 4;
            size_t goff = ((size_t)(kb * FBN + r)) * HDim + c4;
            float4 kv = *(const float4*)(kbase + goff);
            Ks[r * LDQ + c4 + 0] = f2tf32(kv.x);
            Ks[r * LDQ + c4 + 1] = f2tf32(kv.y);
            Ks[r * LDQ + c4 + 2] = f2tf32(kv.z);
            Ks[r * LDQ + c4 + 3] = f2tf32(kv.w);
            float4 vv = *(const float4*)(vbase + goff);
            Vs[r * LDV + c4 + 0] = f2tf32(vv.x);
            Vs[r * LDV + c4 + 1] = f2tf32(vv.y);
            Vs[r * LDV + c4 + 2] = f2tf32(vv.z);
            Vs[r * LDV + c4 + 3] = f2tf32(vv.w);
        }
        __syncthreads();

        // ---- S = Q K^T : warp tile m16 x n64 = 8 mma tiles, K=128 (16 steps)
        float s[8][4];
#pragma unroll
        for (int nt = 0; nt < 8; nt++)
#pragma unroll
            for (int c = 0; c < 4; c++) s[nt][c] = 0.0f;

#pragma unroll
        for (int k0 = 0; k0 < HDim; k0 += 8) {
            uint32_t a0 = Qs[(row0)     * LDQ + k0 + tg];
            uint32_t a1 = Qs[(row0 + 8) * LDQ + k0 + tg];
            uint32_t a2 = Qs[(row0)     * LDQ + k0 + tg + 4];
            uint32_t a3 = Qs[(row0 + 8) * LDQ + k0 + tg + 4];
#pragma unroll
            for (int nt = 0; nt < 8; nt++) {
                uint32_t b0 = Ks[(nt * 8 + g) * LDQ + k0 + tg];
                uint32_t b1 = Ks[(nt * 8 + g) * LDQ + k0 + tg + 4];
                mma_tf32(s[nt], a0, a1, a2, a3, b0, b1);
            }
        }

        // ---- causal mask (only the two diagonal-straddling tiles)
        if (kb >= 2 * qb) {
            int cbase = (kb - 2 * qb) * 64;
#pragma unroll
            for (int nt = 0; nt < 8; nt++) {
                int c0 = cbase + nt * 8 + tg * 2;
                if (c0     > row0)     s[nt][0] = -INFINITY;
                if (c0 + 1 > row0)     s[nt][1] = -INFINITY;
                if (c0     > row0 + 8) s[nt][2] = -INFINITY;
                if (c0 + 1 > row0 + 8) s[nt][3] = -INFINITY;
            }
        }

        // ---- online softmax (warp-local; quad reduction over tg)
        float mx0 = -INFINITY, mx1 = -INFINITY;
#pragma unroll
        for (int nt = 0; nt < 8; nt++) {
            mx0 = fmaxf(mx0, fmaxf(s[nt][0], s[nt][1]));
            mx1 = fmaxf(mx1, fmaxf(s[nt][2], s[nt][3]));
        }
        mx0 = fmaxf(mx0, __shfl_xor_sync(0xffffffffu, mx0, 1));
        mx0 = fmaxf(mx0, __shfl_xor_sync(0xffffffffu, mx0, 2));
        mx1 = fmaxf(mx1, __shfl_xor_sync(0xffffffffu, mx1, 1));
        mx1 = fmaxf(mx1, __shfl_xor_sync(0xffffffffu, mx1, 2));

        float mn0 = fmaxf(m0, mx0);
        float mn1 = fmaxf(m1, mx1);
        float al0 = fexp2(m0 - mn0);
        float al1 = fexp2(m1 - mn1);

        float sum0 = 0.0f, sum1 = 0.0f;
#pragma unroll
        for (int nt = 0; nt < 8; nt++) {
            float p0 = fexp2(s[nt][0] - mn0);
            float p1 = fexp2(s[nt][1] - mn0);
            float p2 = fexp2(s[nt][2] - mn1);
            float p3 = fexp2(s[nt][3] - mn1);
            sum0 += p0 + p1;
            sum1 += p2 + p3;
            uint2 w0; w0.x = f2tf32(p0); w0.y = f2tf32(p1);
            uint2 w1; w1.x = f2tf32(p2); w1.y = f2tf32(p3);
            *(uint2*)&Ps[(row0)     * LDP + nt * 8 + tg * 2] = w0;
            *(uint2*)&Ps[(row0 + 8) * LDP + nt * 8 + tg * 2] = w1;
        }
        sum0 += __shfl_xor_sync(0xffffffffu, sum0, 1);
        sum0 += __shfl_xor_sync(0xffffffffu, sum0, 2);
        sum1 += __shfl_xor_sync(0xffffffffu, sum1, 1);
        sum1 += __shfl_xor_sync(0xffffffffu, sum1, 2);

        l0 = l0 * al0 + sum0;
        l1 = l1 * al1 + sum1;
        m0 = mn0;
        m1 = mn1;

#pragma unroll
        for (int nt = 0; nt < 16; nt++) {
            o[nt][0] *= al0;
            o[nt][1] *= al0;
            o[nt][2] *= al1;
            o[nt][3] *= al1;
        }
        __syncwarp();   // P stores visible to all lanes of this warp

        // ---- O += P V : warp tile m16 x n128 = 16 mma tiles, K=64 (8 steps)
#pragma unroll
        for (int k0 = 0; k0 < FBN; k0 += 8) {
            uint32_t a0 = Ps[(row0)     * LDP + k0 + tg];
            uint32_t a1 = Ps[(row0 + 8) * LDP + k0 + tg];
            uint32_t a2 = Ps[(row0)     * LDP + k0 + tg + 4];
            uint32_t a3 = Ps[(row0 + 8) * LDP + k0 + tg + 4];
#pragma unroll
            for (int nt = 0; nt < 16; nt++) {
                uint32_t b0 = Vs[(k0 + tg)     * LDV + nt * 8 + g];
                uint32_t b1 = Vs[(k0 + tg + 4) * LDV + nt * 8 + g];
                mma_tf32(o[nt], a0, a1, a2, a3, b0, b1);
            }
        }
    }

    // ---- epilogue: normalize, write ctx (B,T,D)
    float inv0 = 1.0f / l0;
    float inv1 = 1.0f / l1;
    int t0 = qb * FBM + row0;
    int t1 = t0 + 8;
    float* p0 = ctx + ((size_t)(b * Tt + t0)) * Dd + h * HDim + tg * 2;
    float* p1 = ctx + ((size_t)(b * Tt + t1)) * Dd + h * HDim + tg * 2;
#pragma unroll
    for (int nt = 0; nt < 16; nt++) {
        *(float2*)(p0 + nt * 8) = make_float2(o[nt][0] * inv0, o[nt][1] * inv0);
        *(float2*)(p1 + nt * 8) = make_float2(o[nt][2] * inv1, o[nt][3] * inv1);
    }
}

// ---------------------------------------------------------------------------
// Launch
// ---------------------------------------------------------------------------
extern "C" void kernel_launch(void* const* d_in, const int* in_sizes, int n_in,
                              void* d_out, int out_size)
{
    const float* x        = (const float*)d_in[0];
    const float* Wq       = (const float*)d_in[1];
    const float* Wk       = (const float*)d_in[2];
    const float* Wv       = (const float*)d_in[3];
    const float* Wo       = (const float*)d_in[4];
    const float* rope_cos = (const float*)d_in[5];
    const float* rope_sin = (const float*)d_in[6];
    float* out = (float*)d_out;

    float *qp, *kp, *vp, *ctxp;
    cudaGetSymbolAddress((void**)&qp,   g_q);
    cudaGetSymbolAddress((void**)&kp,   g_k);
    cudaGetSymbolAddress((void**)&vp,   g_v);
    cudaGetSymbolAddress((void**)&ctxp, g_ctx);

    const int FLASH_SMEM = (FBM * LDQ + FBN * LDQ + FBN * LDV + FBM * LDP) * 4; // 181248 B
    cudaFuncSetAttribute(flash_mma_kernel, cudaFuncAttributeMaxDynamicSharedMemorySize, FLASH_SMEM);

    dim3 ggrid(Dd / 128, Mrows / 128);   // (16, 32)
    gemm_tf32_kernel<<<ggrid, 256>>>(x, Wq, qp, 1);
    gemm_tf32_kernel<<<ggrid, 256>>>(x, Wk, kp, 1);
    gemm_tf32_kernel<<<ggrid, 256>>>(x, Wv, vp, 1);

    int rope_threads_total = Bb * Hh * Tt * 64;
    rope_kernel<<<rope_threads_total / 256, 256>>>(qp, kp, rope_cos, rope_sin);

    dim3 fgrid(Tt / FBM, Bb * Hh);       // (16, 32)
    flash_mma_kernel<<<fgrid, 256, FLASH_SMEM>>>(qp, kp, vp, ctxp);

    gemm_tf32_kernel<<<ggrid, 256>>>(ctxp, Wo, out, 0);
}

// round 12
// speedup vs baseline: 2.3120x; 1.2870x over previous
#include <cuda_runtime.h>
#include <math.h>
#include <stdint.h>

// Problem constants
#define Bb 2
#define Tt 2048
#define Dd 2048
#define Hh 16
#define HDim 128
#define Mrows (Bb*Tt)   // 4096

// Scratch (device globals; no allocation allowed)
__device__ float g_x [Mrows*Dd];        // tf32-rounded x
__device__ float g_wq[Dd*Dd];           // tf32-rounded weights
__device__ float g_wk[Dd*Dd];
__device__ float g_wv[Dd*Dd];
__device__ float g_wo[Dd*Dd];
__device__ float g_q[Bb*Hh*Tt*HDim];    // (B,H,T,HD)
__device__ float g_k[Bb*Hh*Tt*HDim];
__device__ float g_v[Bb*Hh*Tt*HDim];
__device__ float g_ctx[Bb*Tt*Dd];       // (B,T,D), tf32-rounded

__device__ __forceinline__ uint32_t f2tf32(float x) {
    uint32_t r;
    asm("cvt.rna.tf32.f32 %0, %1;" : "=r"(r) : "f"(x));
    return r;
}

__device__ __forceinline__ void mma_tf32(float c[4],
                                         uint32_t a0, uint32_t a1, uint32_t a2, uint32_t a3,
                                         uint32_t b0, uint32_t b1) {
    asm volatile(
        "mma.sync.aligned.m16n8k8.row.col.f32.tf32.tf32.f32 "
        "{%0,%1,%2,%3}, {%4,%5,%6,%7}, {%8,%9}, {%0,%1,%2,%3};"
        : "+f"(c[0]), "+f"(c[1]), "+f"(c[2]), "+f"(c[3])
        : "r"(a0), "r"(a1), "r"(a2), "r"(a3), "r"(b0), "r"(b1));
}

// CVT-free exp2: magic-number range reduction + integer exponent splice.
// f in [-0.5,0.5], degree-5 Taylor: rel err < 3e-6. Zero MUFU, zero CVT.
__device__ __forceinline__ float fexp2(float x) {
    x = fmaxf(x, -126.0f);
    float t  = __fadd_rn(x, 12582912.0f);        // 2^23 * 1.5
    int   i  = __float_as_int(t) << 23;          // integer part -> exponent offset
    float xi = __fsub_rn(t, 12582912.0f);        // nearest-integer value of x
    float f  = __fsub_rn(x, xi);                 // [-0.5, 0.5]
    float p  = 0.0013333558f;
    p = fmaf(p, f, 0.0096181291f);
    p = fmaf(p, f, 0.0555041086f);
    p = fmaf(p, f, 0.2402265069f);
    p = fmaf(p, f, 0.6931471806f);
    p = fmaf(p, f, 1.0f);
    return __int_as_float(__float_as_int(p) + i);
}

// tf32 round-to-nearest via ALU (positive inputs).
__device__ __forceinline__ uint32_t rtf32_pos(float v) {
    return ((uint32_t)__float_as_int(v) + 0x1000u) & 0xFFFFE000u;
}

// cp.async helpers
__device__ __forceinline__ void cpa16(uint32_t saddr, const void* gptr) {
    asm volatile("cp.async.cg.shared.global [%0], [%1], 16;" :: "r"(saddr), "l"(gptr));
}
__device__ __forceinline__ void cpa_commit() { asm volatile("cp.async.commit_group;"); }
__device__ __forceinline__ void cpa_wait0()  { asm volatile("cp.async.wait_group 0;"); }
__device__ __forceinline__ void cpa_wait1()  { asm volatile("cp.async.wait_group 1;"); }

// ---------------------------------------------------------------------------
// tf32 pre-round pass (elementwise, float4)
// ---------------------------------------------------------------------------
__global__ __launch_bounds__(256)
void round_kernel(const float4* __restrict__ in, float4* __restrict__ out)
{
    int i = blockIdx.x * 256 + threadIdx.x;
    float4 v = in[i];
    uint4 r;
    r.x = f2tf32(v.x); r.y = f2tf32(v.y); r.z = f2tf32(v.z); r.w = f2tf32(v.w);
    *(uint4*)&out[i] = r;
}

// ---------------------------------------------------------------------------
// TF32 GEMM, natural-layout smem + 2-stage cp.async. Inputs pre-rounded tf32.
// C[m,n] = sum_k A[m,k]*W[n,k].  M=4096, N=K=2048.
// Block 128x128, BK=16, 8 warps (4m x 2n), warp 32x64.
// mode 0: row-major out; 1: scatter (B,H,T,HD); 2: scatter + tf32 round.
// ---------------------------------------------------------------------------
#define GLD 20   // row stride words; lane->bank map of frag reads is a permutation

__global__ __launch_bounds__(256)
void gemm_tf32_kernel(const float* __restrict__ A, const float* __restrict__ W,
                      float* __restrict__ out, int mode)
{
    const int K = Dd;
    const int N = Dd;
    __shared__ uint32_t As[2][128 * GLD];
    __shared__ uint32_t Bs[2][128 * GLD];

    const int tid    = threadIdx.x;
    const int lane   = tid & 31;
    const int warp   = tid >> 5;
    const int warp_m = warp >> 1;
    const int warp_n = warp & 1;
    const int g      = lane >> 2;
    const int tg     = lane & 3;

    const int m0 = blockIdx.y * 128;
    const int n0 = blockIdx.x * 128;
    const int m_warp = warp_m * 32;
    const int n_warp = warp_n * 64;

    const float* Aptr = A + (size_t)m0 * K;
    const float* Wptr = W + (size_t)n0 * K;

    uint32_t sA = (uint32_t)__cvta_generic_to_shared(&As[0][0]);
    uint32_t sB = (uint32_t)__cvta_generic_to_shared(&Bs[0][0]);

    float acc[2][8][4];
#pragma unroll
    for (int mt = 0; mt < 2; mt++)
#pragma unroll
        for (int nt = 0; nt < 8; nt++)
#pragma unroll
            for (int c = 0; c < 4; c++) acc[mt][nt][c] = 0.0f;

    const int NK = K / 16;   // 128

    // prologue: stage 0 (512 chunks of 16B per operand: 128 rows x 4 chunks)
    {
#pragma unroll
        for (int j = 0; j < 2; j++) {
            int c = tid + j * 256;
            int r = c >> 2, q = c & 3;
            cpa16(sA + (r * GLD + q * 4) * 4, Aptr + (size_t)r * K + q * 4);
            cpa16(sB + (r * GLD + q * 4) * 4, Wptr + (size_t)r * K + q * 4);
        }
        cpa_commit();
    }

    for (int kt = 0; kt < NK; kt++) {
        int cur = kt & 1;
        if (kt + 1 < NK) {
            int nxt = cur ^ 1;
#pragma unroll
            for (int j = 0; j < 2; j++) {
                int c = tid + j * 256;
                int r = c >> 2, q = c & 3;
                cpa16(sA + (nxt * 128 * GLD + r * GLD + q * 4) * 4,
                      Aptr + (size_t)r * K + (kt + 1) * 16 + q * 4);
                cpa16(sB + (nxt * 128 * GLD + r * GLD + q * 4) * 4,
                      Wptr + (size_t)r * K + (kt + 1) * 16 + q * 4);
            }
            cpa_commit();
            cpa_wait1();
        } else {
            cpa_wait0();
        }
        __syncthreads();

        const uint32_t* Ac = &As[cur][0];
        const uint32_t* Bc = &Bs[cur][0];
#pragma unroll
        for (int k0 = 0; k0 < 16; k0 += 8) {
            uint32_t a[2][4];
#pragma unroll
            for (int mt = 0; mt < 2; mt++) {
                int mb = m_warp + mt * 16;
                a[mt][0] = Ac[(mb + g)     * GLD + k0 + tg];
                a[mt][1] = Ac[(mb + g + 8) * GLD + k0 + tg];
                a[mt][2] = Ac[(mb + g)     * GLD + k0 + tg + 4];
                a[mt][3] = Ac[(mb + g + 8) * GLD + k0 + tg + 4];
            }
            uint32_t b[8][2];
#pragma unroll
            for (int nt = 0; nt < 8; nt++) {
                int nb = n_warp + nt * 8;
                b[nt][0] = Bc[(nb + g) * GLD + k0 + tg];
                b[nt][1] = Bc[(nb + g) * GLD + k0 + tg + 4];
            }
#pragma unroll
            for (int mt = 0; mt < 2; mt++)
#pragma unroll
                for (int nt = 0; nt < 8; nt++)
                    mma_tf32(acc[mt][nt], a[mt][0], a[mt][1], a[mt][2], a[mt][3],
                             b[nt][0], b[nt][1]);
        }
        __syncthreads();   // done reading buf[cur] before it is overwritten
    }

    if (mode == 0) {
#pragma unroll
        for (int mt = 0; mt < 2; mt++) {
#pragma unroll
            for (int half = 0; half < 2; half++) {
                int m = m0 + m_warp + mt * 16 + g + half * 8;
                float* rowp = out + (size_t)m * N + n0 + n_warp + tg * 2;
#pragma unroll
                for (int nt = 0; nt < 8; nt++)
                    *(float2*)(rowp + nt * 8) =
                        make_float2(acc[mt][nt][half * 2], acc[mt][nt][half * 2 + 1]);
            }
        }
    } else {
        int h = n0 >> 7;
#pragma unroll
        for (int mt = 0; mt < 2; mt++) {
#pragma unroll
            for (int half = 0; half < 2; half++) {
                int m  = m0 + m_warp + mt * 16 + g + half * 8;
                int bI = m >> 11;
                int t  = m & (Tt - 1);
                float* rowp = out + (((size_t)(bI * Hh + h) * Tt + t) * HDim)
                              + n_warp + tg * 2;
#pragma unroll
                for (int nt = 0; nt < 8; nt++) {
                    float v0 = acc[mt][nt][half * 2];
                    float v1 = acc[mt][nt][half * 2 + 1];
                    if (mode == 2) {
                        v0 = __uint_as_float(f2tf32(v0));
                        v1 = __uint_as_float(f2tf32(v1));
                    }
                    *(float2*)(rowp + nt * 8) = make_float2(v0, v1);
                }
            }
        }
    }
}

// ---------------------------------------------------------------------------
// RoPE: rotates q,k; q additionally scaled by (1/sqrt(HD))*log2(e).
// Outputs tf32-rounded (flash consumes raw bits).
// ---------------------------------------------------------------------------
__global__ __launch_bounds__(256)
void rope_kernel(float* __restrict__ q, float* __restrict__ k,
                 const float* __restrict__ cosp, const float* __restrict__ sinp)
{
    const float qs = 0.08838834764831845f * 1.4426950408889634f;
    int gid = blockIdx.x * 256 + threadIdx.x;
    int row = gid >> 6;
    int i   = gid & 63;
    int t   = row & (Tt - 1);

    float c1 = cosp[t * HDim + i];
    float s1 = sinp[t * HDim + i];
    float c2 = cosp[t * HDim + 64 + i];
    float s2 = sinp[t * HDim + 64 + i];

    float* qp = q + (size_t)row * HDim;
    float qa = qp[i], qb = qp[i + 64];
    ((uint32_t*)qp)[i]      = f2tf32((c1 * qa - s1 * qb) * qs);
    ((uint32_t*)qp)[i + 64] = f2tf32((c2 * qb + s2 * qa) * qs);

    float* kp = k + (size_t)row * HDim;
    float ka = kp[i], kb = kp[i + 64];
    ((uint32_t*)kp)[i]      = f2tf32(c1 * ka - s1 * kb);
    ((uint32_t*)kp)[i + 64] = f2tf32(c2 * kb + s2 * ka);
}

// ---------------------------------------------------------------------------
// Flash attention, tf32 mma, cp.async pipelined. Inputs pre-rounded tf32.
// BM=128, BN=64, HD=128. 8 warps, warp w owns rows [16w,16w+16).
// Smem (words): Qs[128][132] | Ks[2][64][132] | Vs[64][136] | Ps[128][76]
// Per row: 128 floats = 32 chunks of 16B.
// ---------------------------------------------------------------------------
#define FBM 128
#define FBN 64
#define LDQ 132   // mod 32 == 4
#define LDV 136   // mod 32 == 8
#define LDP 76    // mod 32 == 12

#define Q_WORDS (FBM*LDQ)          // 16896
#define K_WORDS (FBN*LDQ)          // 8448
#define V_WORDS (FBN*LDV)          // 8704
#define P_WORDS (FBM*LDP)          // 9728
#define FLASH_WORDS (Q_WORDS + 2*K_WORDS + V_WORDS + P_WORDS)

__global__ __launch_bounds__(256, 1)
void flash_mma_kernel(const float* __restrict__ q, const float* __restrict__ k,
                      const float* __restrict__ v, float* __restrict__ ctx)
{
    extern __shared__ uint32_t smu[];
    uint32_t* Qs = smu;
    uint32_t* Ks = Qs + Q_WORDS;          // 2 buffers
    uint32_t* Vs = Ks + 2 * K_WORDS;
    uint32_t* Ps = Vs + V_WORDS;

    const int tid  = threadIdx.x;
    const int lane = tid & 31;
    const int w    = tid >> 5;
    const int g    = lane >> 2;
    const int tg   = lane & 3;

    const int qb = blockIdx.x;            // 0..15
    const int bh = blockIdx.y;            // 0..31
    const int b  = bh >> 4;
    const int h  = bh & 15;

    const float* qbase = q + ((size_t)bh * Tt + (size_t)qb * FBM) * HDim;
    const float* kbase = k + (size_t)bh * Tt * HDim;
    const float* vbase = v + (size_t)bh * Tt * HDim;

    uint32_t sQ = (uint32_t)__cvta_generic_to_shared(Qs);
    uint32_t sK = (uint32_t)__cvta_generic_to_shared(Ks);
    uint32_t sV = (uint32_t)__cvta_generic_to_shared(Vs);

    // prologue: Q = 4096 chunks (128 rows x 32 chunks); K0,V0 = 2048 chunks each
#pragma unroll
    for (int j = 0; j < 16; j++) {
        int c = tid + j * 256;            // 0..4095
        int r = c >> 5, qq = c & 31;
        cpa16(sQ + (r * LDQ + qq * 4) * 4, qbase + (size_t)r * HDim + qq * 4);
    }
    cpa_commit();
#pragma unroll
    for (int j = 0; j < 8; j++) {
        int c = tid + j * 256;            // 0..2047
        int r = c >> 5, qq = c & 31;
        cpa16(sK + (r * LDQ + qq * 4) * 4, kbase + (size_t)r * HDim + qq * 4);
        cpa16(sV + (r * LDV + qq * 4) * 4, vbase + (size_t)r * HDim + qq * 4);
    }
    cpa_commit();
    cpa_wait0();
    __syncthreads();

    const int row0 = 16 * w + g;

    float m0 = -INFINITY, m1 = -INFINITY;
    float l0 = 0.0f, l1 = 0.0f;
    float o[16][4];
#pragma unroll
    for (int nt = 0; nt < 16; nt++)
#pragma unroll
        for (int c = 0; c < 4; c++) o[nt][c] = 0.0f;

    const int nkb = 2 * qb + 2;
    for (int kb = 0; kb < nkb; kb++) {
        int cur = kb & 1;
        // prefetch next K tile into other buffer
        if (kb + 1 < nkb) {
            uint32_t dst = sK + ((cur ^ 1) * K_WORDS) * 4;
            const float* src = kbase + (size_t)(kb + 1) * FBN * HDim;
#pragma unroll
            for (int j = 0; j < 8; j++) {
                int c = tid + j * 256;
                int r = c >> 5, qq = c & 31;
                cpa16(dst + (r * LDQ + qq * 4) * 4, src + (size_t)r * HDim + qq * 4);
            }
            cpa_commit();
        }
        if (kb > 0) {
            if (kb + 1 < nkb) cpa_wait1(); else cpa_wait0();
            __syncthreads();
        }

        const uint32_t* Kc = Ks + cur * K_WORDS;

        // ---- S = Q K^T
        float s[8][4];
#pragma unroll
        for (int nt = 0; nt < 8; nt++)
#pragma unroll
            for (int c = 0; c < 4; c++) s[nt][c] = 0.0f;

#pragma unroll
        for (int k0 = 0; k0 < HDim; k0 += 8) {
            uint32_t a0 = Qs[(row0)     * LDQ + k0 + tg];
            uint32_t a1 = Qs[(row0 + 8) * LDQ + k0 + tg];
            uint32_t a2 = Qs[(row0)     * LDQ + k0 + tg + 4];
            uint32_t a3 = Qs[(row0 + 8) * LDQ + k0 + tg + 4];
#pragma unroll
            for (int nt = 0; nt < 8; nt++) {
                uint32_t b0 = Kc[(nt * 8 + g) * LDQ + k0 + tg];
                uint32_t b1 = Kc[(nt * 8 + g) * LDQ + k0 + tg + 4];
                mma_tf32(s[nt], a0, a1, a2, a3, b0, b1);
            }
        }

        // ---- causal mask (diagonal-straddling tiles only)
        if (kb >= 2 * qb) {
            int cbase = (kb - 2 * qb) * 64;
#pragma unroll
            for (int nt = 0; nt < 8; nt++) {
                int c0 = cbase + nt * 8 + tg * 2;
                if (c0     > row0)     s[nt][0] = -INFINITY;
                if (c0 + 1 > row0)     s[nt][1] = -INFINITY;
                if (c0     > row0 + 8) s[nt][2] = -INFINITY;
                if (c0 + 1 > row0 + 8) s[nt][3] = -INFINITY;
            }
        }

        // ---- online softmax (warp-local)
        float mx0 = -INFINITY, mx1 = -INFINITY;
#pragma unroll
        for (int nt = 0; nt < 8; nt++) {
            mx0 = fmaxf(mx0, fmaxf(s[nt][0], s[nt][1]));
            mx1 = fmaxf(mx1, fmaxf(s[nt][2], s[nt][3]));
        }
        mx0 = fmaxf(mx0, __shfl_xor_sync(0xffffffffu, mx0, 1));
        mx0 = fmaxf(mx0, __shfl_xor_sync(0xffffffffu, mx0, 2));
        mx1 = fmaxf(mx1, __shfl_xor_sync(0xffffffffu, mx1, 1));
        mx1 = fmaxf(mx1, __shfl_xor_sync(0xffffffffu, mx1, 2));

        float mn0 = fmaxf(m0, mx0);
        float mn1 = fmaxf(m1, mx1);
        float al0 = fexp2(m0 - mn0);
        float al1 = fexp2(m1 - mn1);

        float sum0 = 0.0f, sum1 = 0.0f;
#pragma unroll
        for (int nt = 0; nt < 8; nt++) {
            float p0 = fexp2(s[nt][0] - mn0);
            float p1 = fexp2(s[nt][1] - mn0);
            float p2 = fexp2(s[nt][2] - mn1);
            float p3 = fexp2(s[nt][3] - mn1);
            sum0 += p0 + p1;
            sum1 += p2 + p3;
            uint2 w0; w0.x = rtf32_pos(p0); w0.y = rtf32_pos(p1);
            uint2 w1; w1.x = rtf32_pos(p2); w1.y = rtf32_pos(p3);
            *(uint2*)&Ps[(row0)     * LDP + nt * 8 + tg * 2] = w0;
            *(uint2*)&Ps[(row0 + 8) * LDP + nt * 8 + tg * 2] = w1;
        }
        sum0 += __shfl_xor_sync(0xffffffffu, sum0, 1);
        sum0 += __shfl_xor_sync(0xffffffffu, sum0, 2);
        sum1 += __shfl_xor_sync(0xffffffffu, sum1, 1);
        sum1 += __shfl_xor_sync(0xffffffffu, sum1, 2);

        l0 = l0 * al0 + sum0;
        l1 = l1 * al1 + sum1;
        m0 = mn0;
        m1 = mn1;

#pragma unroll
        for (int nt = 0; nt < 16; nt++) {
            o[nt][0] *= al0;
            o[nt][1] *= al0;
            o[nt][2] *= al1;
            o[nt][3] *= al1;
        }
        __syncwarp();

        // ---- O += P V
#pragma unroll
        for (int k0 = 0; k0 < FBN; k0 += 8) {
            uint32_t a0 = Ps[(row0)     * LDP + k0 + tg];
            uint32_t a1 = Ps[(row0 + 8) * LDP + k0 + tg];
            uint32_t a2 = Ps[(row0)     * LDP + k0 + tg + 4];
            uint32_t a3 = Ps[(row0 + 8) * LDP + k0 + tg + 4];
#pragma unroll
            for (int nt = 0; nt < 16; nt++) {
                uint32_t b0 = Vs[(k0 + tg)     * LDV + nt * 8 + g];
                uint32_t b1 = Vs[(k0 + tg + 4) * LDV + nt * 8 + g];
                mma_tf32(o[nt], a0, a1, a2, a3, b0, b1);
            }
        }
        __syncthreads();   // everyone done reading Vs before overwrite

        // prefetch next V tile (single buffer, overlaps next iter's S)
        if (kb + 1 < nkb) {
            const float* src = vbase + (size_t)(kb + 1) * FBN * HDim;
#pragma unroll
            for (int j = 0; j < 8; j++) {
                int c = tid + j * 256;
                int r = c >> 5, qq = c & 31;
                cpa16(sV + (r * LDV + qq * 4) * 4, src + (size_t)r * HDim + qq * 4);
            }
            cpa_commit();
        }
    }

    // ---- epilogue: normalize, round to tf32 (feeds final GEMM), write ctx
    float inv0 = 1.0f / l0;
    float inv1 = 1.0f / l1;
    int t0 = qb * FBM + row0;
    int t1 = t0 + 8;
    uint32_t* p0 = (uint32_t*)(ctx + ((size_t)(b * Tt + t0)) * Dd + h * HDim + tg * 2);
    uint32_t* p1 = (uint32_t*)(ctx + ((size_t)(b * Tt + t1)) * Dd + h * HDim + tg * 2);
#pragma unroll
    for (int nt = 0; nt < 16; nt++) {
        uint2 w0, w1;
        w0.x = f2tf32(o[nt][0] * inv0); w0.y = f2tf32(o[nt][1] * inv0);
        w1.x = f2tf32(o[nt][2] * inv1); w1.y = f2tf32(o[nt][3] * inv1);
        *(uint2*)(p0 + nt * 8) = w0;
        *(uint2*)(p1 + nt * 8) = w1;
    }
}

// ---------------------------------------------------------------------------
// Launch
// ---------------------------------------------------------------------------
extern "C" void kernel_launch(void* const* d_in, const int* in_sizes, int n_in,
                              void* d_out, int out_size)
{
    const float* x        = (const float*)d_in[0];
    const float* Wq       = (const float*)d_in[1];
    const float* Wk       = (const float*)d_in[2];
    const float* Wv       = (const float*)d_in[3];
    const float* Wo       = (const float*)d_in[4];
    const float* rope_cos = (const float*)d_in[5];
    const float* rope_sin = (const float*)d_in[6];
    float* out = (float*)d_out;

    float *xp, *wqp, *wkp, *wvp, *wop, *qp, *kp, *vp, *ctxp;
    cudaGetSymbolAddress((void**)&xp,   g_x);
    cudaGetSymbolAddress((void**)&wqp,  g_wq);
    cudaGetSymbolAddress((void**)&wkp,  g_wk);
    cudaGetSymbolAddress((void**)&wvp,  g_wv);
    cudaGetSymbolAddress((void**)&wop,  g_wo);
    cudaGetSymbolAddress((void**)&qp,   g_q);
    cudaGetSymbolAddress((void**)&kp,   g_k);
    cudaGetSymbolAddress((void**)&vp,   g_v);
    cudaGetSymbolAddress((void**)&ctxp, g_ctx);

    const int FLASH_SMEM = FLASH_WORDS * 4;  // 208896 B
    cudaFuncSetAttribute(flash_mma_kernel, cudaFuncAttributeMaxDynamicSharedMemorySize, FLASH_SMEM);

    // Pre-round inputs to tf32 (removes CVT from all GEMM/flash hot loops)
    round_kernel<<<(Mrows*Dd)/1024, 256>>>((const float4*)x,  (float4*)xp);
    round_kernel<<<(Dd*Dd)/1024,    256>>>((const float4*)Wq, (float4*)wqp);
    round_kernel<<<(Dd*Dd)/1024,    256>>>((const float4*)Wk, (float4*)wkp);
    round_kernel<<<(Dd*Dd)/1024,    256>>>((const float4*)Wv, (float4*)wvp);
    round_kernel<<<(Dd*Dd)/1024,    256>>>((const float4*)Wo, (float4*)wop);

    dim3 ggrid(Dd / 128, Mrows / 128);   // (16, 32)
    gemm_tf32_kernel<<<ggrid, 256>>>(xp, wqp, qp, 1);
    gemm_tf32_kernel<<<ggrid, 256>>>(xp, wkp, kp, 1);
    gemm_tf32_kernel<<<ggrid, 256>>>(xp, wvp, vp, 2);   // V: round (flash consumes raw)

    int rope_threads_total = Bb * Hh * Tt * 64;
    rope_kernel<<<rope_threads_total / 256, 256>>>(qp, kp, rope_cos, rope_sin);

    dim3 fgrid(Tt / FBM, Bb * Hh);       // (16, 32)
    flash_mma_kernel<<<fgrid, 256, FLASH_SMEM>>>(qp, kp, vp, ctxp);

    gemm_tf32_kernel<<<ggrid, 256>>>(ctxp, wop, out, 0);
}